// round 10
// baseline (speedup 1.0000x reference)
#include <cuda_runtime.h>
#include <math.h>

#define B_SZ   1024
#define HID    384
#define MH     300
#define OPAD   320   // padded row stride; cols 300..319 stay zero (zero-init globals)
#define NJT    16
#define NTILE  256

typedef unsigned long long u64;

// Scratch (device globals; allocations forbidden). Zero-initialized at load;
// padding columns are never written, so they remain exactly 0.0f.
__device__ float g_s1[B_SZ * HID];
__device__ float g_s2[B_SZ * HID];
__device__ float g_Axb[B_SZ * OPAD];
__device__ float g_By [B_SZ * OPAD];
__device__ float g_klpart[B_SZ];
__device__ float g_T0[B_SZ];
__device__ float g_rowpart[NJT * B_SZ];   // [jt][i] — coalesced reads & writes
__device__ unsigned g_done;               // arrival counter; self-resetting

__device__ __forceinline__ float softplusf(float x) {
    return fmaxf(x, 0.f) + log1pf(expf(-fabsf(x)));
}

// Packed f32x2 ops on u64-resident data
__device__ __forceinline__ u64 f2add_u(u64 a, u64 b) {
    u64 d; asm("add.rn.f32x2 %0, %1, %2;" : "=l"(d) : "l"(a), "l"(b)); return d;
}
__device__ __forceinline__ u64 f2fma_u(u64 a, u64 b, u64 c) {
    u64 d; asm("fma.rn.f32x2 %0, %1, %2, %3;" : "=l"(d) : "l"(a), "l"(b), "l"(c)); return d;
}
// Free unpack: names the two halves of the register pair (no SASS mov needed)
__device__ __forceinline__ void f2unpack(u64 a, float& lo, float& hi) {
    asm("mov.b64 {%0,%1}, %2;" : "=f"(lo), "=f"(hi) : "l"(a));
}
__device__ __forceinline__ float f2hsum(u64 a) {
    float lo, hi; f2unpack(a, lo, hi); return lo + hi;
}
__device__ __forceinline__ u64 fpack(float x, float y) {
    u64 d; asm("mov.b64 %0, {%1,%2};" : "=l"(d) : "f"(x), "f"(y)); return d;
}

// ---------------------------------------------------------------------------
// K1: per-batch-row fused  einsum -> (mu,sig) -> sample -> KL partial
// grid 1024, block 192. HBM-bound (176 MB, measured 75% SOL).
// ---------------------------------------------------------------------------
__global__ __launch_bounds__(192) void k1_fuse(
    const float* __restrict__ zl, const float* __restrict__ zv,
    const float* __restrict__ wl_g, const float* __restrict__ bl_g,
    const float* __restrict__ wv_g, const float* __restrict__ bv_g,
    const float* __restrict__ eps1, const float* __restrict__ eps2)
{
    __shared__ float z1s[768], z2s[768];
    __shared__ float wls[20], wvs[36];
    __shared__ float redw[6];
    const int b = blockIdx.x, t = threadIdx.x;
    if (t < 20) wls[t] = wl_g[t];
    if (t >= 32 && t < 68) wvs[t - 32] = wv_g[t - 32];
    __syncthreads();
    const float bl = bl_g[0], bv = bv_g[0];
    {
        const float4* p = (const float4*)(zl + (size_t)b * 20 * 768) + t;
        float4 a = make_float4(bl, bl, bl, bl);
        #pragma unroll
        for (int s = 0; s < 20; ++s) {
            float4 v = p[s * 192];
            float w = wls[s];
            a.x = fmaf(v.x, w, a.x); a.y = fmaf(v.y, w, a.y);
            a.z = fmaf(v.z, w, a.z); a.w = fmaf(v.w, w, a.w);
        }
        ((float4*)z1s)[t] = a;
    }
    {
        const float4* p = (const float4*)(zv + (size_t)b * 36 * 768) + t;
        float4 a = make_float4(bv, bv, bv, bv);
        #pragma unroll
        for (int s = 0; s < 36; ++s) {
            float4 v = p[s * 192];
            float w = wvs[s];
            a.x = fmaf(v.x, w, a.x); a.y = fmaf(v.y, w, a.y);
            a.z = fmaf(v.z, w, a.z); a.w = fmaf(v.w, w, a.w);
        }
        ((float4*)z2s)[t] = a;
    }
    __syncthreads();
    float klacc = 0.f;
    #pragma unroll
    for (int q = 0; q < 2; ++q) {
        int k = t + q * 192;
        float mu1 = z1s[k], mu2 = z2s[k];
        float sg1 = softplusf(z1s[k + HID]) + 1e-7f;
        float sg2 = softplusf(z2s[k + HID]) + 1e-7f;
        float e1 = eps1[b * HID + k], e2 = eps2[b * HID + k];
        float s1v = fmaf(sg1, e1, mu1);
        float s2v = fmaf(sg2, e2, mu2);
        g_s1[b * HID + k] = s1v;
        g_s2[b * HID + k] = s2v;
        float d1 = (s1v - mu2) / sg2;
        float d2 = (s2v - mu1) / sg1;
        klacc += 0.5f * (d1 * d1 + d2 * d2 - e1 * e1 - e2 * e2);
    }
    #pragma unroll
    for (int off = 16; off > 0; off >>= 1)
        klacc += __shfl_xor_sync(0xFFFFFFFFu, klacc, off);
    if ((t & 31) == 0) redw[t >> 5] = klacc;
    __syncthreads();
    if (t == 0)
        g_klpart[b] = redw[0] + redw[1] + redw[2] + redw[3] + redw[4] + redw[5];
}

// ---------------------------------------------------------------------------
// K2: Axb = s1 @ W1x^T + b1 ;  By = s2 @ W1y^T
// grid (16,5,2), block 256.  Tile 64x64, u64-packed over k, 4x4/thread.
// (Pure FFMA2 chain — no scalar interludes, so no pack movs here.)
// ---------------------------------------------------------------------------
__global__ __launch_bounds__(256) void k2_gemm(
    const float* __restrict__ W1, const float* __restrict__ b1)
{
    __shared__ u64 As[64][17];
    __shared__ u64 Ws[64][17];

    const int z  = blockIdx.z;
    const int r0 = blockIdx.x * 64;
    const int c0 = blockIdx.y * 64;
    const float* S = z ? g_s2 : g_s1;
    float*       O = z ? g_By : g_Axb;
    const int koff = z ? HID : 0;

    const int t  = threadIdx.x;
    const int tj = t & 15;
    const int ti = t >> 4;

    u64 acc[4][4];
    #pragma unroll
    for (int r = 0; r < 4; ++r)
        #pragma unroll
        for (int c = 0; c < 4; ++c) acc[r][c] = 0ull;

    for (int kk2 = 0; kk2 < 192; kk2 += 16) {
        __syncthreads();
        #pragma unroll
        for (int i = 0; i < 4; ++i) {
            int e = t + i * 256;
            int row = e >> 4, k2 = e & 15;
            As[row][k2] = *(const u64*)&S[(r0 + row) * HID + (kk2 + k2) * 2];
            int col = c0 + row;
            Ws[row][k2] = (col < MH)
                ? *(const u64*)&W1[col * 768 + koff + (kk2 + k2) * 2] : 0ull;
        }
        __syncthreads();
        #pragma unroll 4
        for (int k2 = 0; k2 < 16; ++k2) {
            u64 a[4], w[4];
            #pragma unroll
            for (int r = 0; r < 4; ++r) a[r] = As[ti + 16 * r][k2];
            #pragma unroll
            for (int c = 0; c < 4; ++c) w[c] = Ws[tj + 16 * c][k2];
            #pragma unroll
            for (int r = 0; r < 4; ++r)
                #pragma unroll
                for (int c = 0; c < 4; ++c)
                    acc[r][c] = f2fma_u(a[r], w[c], acc[r][c]);
        }
    }
    #pragma unroll
    for (int r = 0; r < 4; ++r) {
        int row = r0 + ti + 16 * r;
        #pragma unroll
        for (int c = 0; c < 4; ++c) {
            int col = c0 + tj + 16 * c;
            if (col < MH) {
                float v = f2hsum(acc[r][c]);
                if (z == 0) v += b1[col];
                O[row * OPAD + col] = v;
            }
        }
    }
}

// ---------------------------------------------------------------------------
// K3: pairwise grid + fused final reduction in last-arriving CTA.
// u[i][j] = sum_k relu(Axb[j,k] + By[i,k]) * w2[k]
// grid (16 jt, 16 it), block 256. 64x64 tile, 4x4 pairs/thread,
// register-prefetch pipeline.  Diagonal blocks write T0.
// Inner pair = FADD2 + 2 FMNMX + 2 scalar FFMA (scalar accs: no pack movs).
// ---------------------------------------------------------------------------
__global__ __launch_bounds__(256) void k3_pair(
    const float* __restrict__ W2, const float* __restrict__ b2g,
    float* __restrict__ out)
{
    __shared__ u64 Bys[64][17];
    __shared__ u64 Axs[64][17];
    __shared__ u64 w2s[160];
    __shared__ float rowred[64][17];
    __shared__ int sLast;
    __shared__ double sred[3][8];

    const int jt = blockIdx.x;
    const int it = blockIdx.y;
    const int i0 = it * 64, j0 = jt * 64;
    const int t  = threadIdx.x;
    const int tj = t & 15;
    const int ti = t >> 4;

    if (t < 160) {
        int k = 2 * t;
        float2 w = make_float2(k < MH ? W2[k] : 0.f,
                               k + 1 < MH ? W2[k + 1] : 0.f);
        w2s[t] = *(const u64*)&w;
    }

    // float4 prefetch mapping: unit u in [0,512): row=u>>3, f4=u&7
    const int rA = t >> 3,          fA = t & 7;
    const int rB = (t + 256) >> 3,  fB = t & 7;
    const float* byA = &g_By [(i0 + rA) * OPAD + fA * 4];
    const float* byB = &g_By [(i0 + rB) * OPAD + fB * 4];
    const float* axA = &g_Axb[(j0 + rA) * OPAD + fA * 4];
    const float* axB = &g_Axb[(j0 + rB) * OPAD + fB * 4];

    float accL[4][4], accH[4][4];
    #pragma unroll
    for (int r = 0; r < 4; ++r)
        #pragma unroll
        for (int c = 0; c < 4; ++c) { accL[r][c] = 0.f; accH[r][c] = 0.f; }

    float4 pb0 = *(const float4*)(byA);
    float4 pb1 = *(const float4*)(byB);
    float4 pa0 = *(const float4*)(axA);
    float4 pa1 = *(const float4*)(axB);

    for (int c = 0; c < 10; ++c) {
        __syncthreads();
        Bys[rA][2 * fA]     = fpack(pb0.x, pb0.y);
        Bys[rA][2 * fA + 1] = fpack(pb0.z, pb0.w);
        Bys[rB][2 * fB]     = fpack(pb1.x, pb1.y);
        Bys[rB][2 * fB + 1] = fpack(pb1.z, pb1.w);
        Axs[rA][2 * fA]     = fpack(pa0.x, pa0.y);
        Axs[rA][2 * fA + 1] = fpack(pa0.z, pa0.w);
        Axs[rB][2 * fB]     = fpack(pa1.x, pa1.y);
        Axs[rB][2 * fB + 1] = fpack(pa1.z, pa1.w);
        __syncthreads();
        if (c < 9) {
            int off = (c + 1) * 32;
            pb0 = *(const float4*)(byA + off);
            pb1 = *(const float4*)(byB + off);
            pa0 = *(const float4*)(axA + off);
            pa1 = *(const float4*)(axB + off);
        }
        #pragma unroll 4
        for (int k2 = 0; k2 < 16; ++k2) {
            float wlo, whi;
            f2unpack(w2s[c * 16 + k2], wlo, whi);
            u64 a[4], b[4];
            #pragma unroll
            for (int cc = 0; cc < 4; ++cc) a[cc] = Axs[tj + 16 * cc][k2];
            #pragma unroll
            for (int r = 0; r < 4; ++r) b[r] = Bys[ti + 16 * r][k2];
            #pragma unroll
            for (int r = 0; r < 4; ++r)
                #pragma unroll
                for (int cc = 0; cc < 4; ++cc) {
                    u64 s = f2add_u(a[cc], b[r]);
                    float lo, hi;
                    f2unpack(s, lo, hi);           // free half-naming
                    accL[r][cc] = fmaf(fmaxf(lo, 0.f), wlo, accL[r][cc]);
                    accH[r][cc] = fmaf(fmaxf(hi, 0.f), whi, accH[r][cc]);
                }
        }
    }

    const float b2v = b2g[0];

    // Diagonal blocks: T0[i] = softplus(u[i][i] + b2)
    if (jt == it && tj == ti) {
        #pragma unroll
        for (int r = 0; r < 4; ++r)
            g_T0[i0 + ti + 16 * r] =
                softplusf(accL[r][r] + accH[r][r] + b2v);
    }

    __syncthreads();
    #pragma unroll
    for (int r = 0; r < 4; ++r) {
        float e = 0.f;
        #pragma unroll
        for (int cc = 0; cc < 4; ++cc)
            e += expf(accL[r][cc] + accH[r][cc] + b2v);
        rowred[ti + 16 * r][tj] = e;
    }
    __syncthreads();
    if (t < 64) {
        float s = 0.f;
        #pragma unroll
        for (int cc = 0; cc < 16; ++cc) s += rowred[t][cc];
        g_rowpart[jt * B_SZ + i0 + t] = s;
    }

    // ---- last-arriving CTA does the final reduction ----
    __threadfence();
    __syncthreads();
    if (t == 0) {
        unsigned old = atomicAdd(&g_done, 1u);
        sLast = (old == NTILE - 1u);
    }
    __syncthreads();
    if (!sLast) return;
    __threadfence();   // acquire: all CTAs' writes visible

    double kl = 0.0, t0 = 0.0, L = 0.0;
    #pragma unroll
    for (int q = 0; q < 4; ++q) {
        int i = t + q * 256;
        float rs = 0.f;
        #pragma unroll
        for (int j = 0; j < NJT; ++j)     // coalesced per warp
            rs += g_rowpart[j * B_SZ + i];
        kl += (double)g_klpart[i];
        t0 += (double)g_T0[i];
        // logsumexp_j softplus(u) = log(B + sum_j e^u)
        L  += (double)logf((float)B_SZ + rs);
    }
    #pragma unroll
    for (int off = 16; off > 0; off >>= 1) {
        kl += __shfl_xor_sync(0xFFFFFFFFu, kl, off);
        t0 += __shfl_xor_sync(0xFFFFFFFFu, t0, off);
        L  += __shfl_xor_sync(0xFFFFFFFFu, L,  off);
    }
    if ((t & 31) == 0) {
        sred[0][t >> 5] = kl; sred[1][t >> 5] = t0; sred[2][t >> 5] = L;
    }
    __syncthreads();
    if (t == 0) {
        double a = 0, b = 0, c = 0;
        #pragma unroll
        for (int i = 0; i < 8; ++i) {
            a += sred[0][i]; b += sred[1][i]; c += sred[2][i];
        }
        double d_skl = a / (double)B_SZ * 0.5;
        double t0m   = b / (double)B_SZ;
        double meanL = c / (double)B_SZ;
        double lower = t0m - (meanL - log((double)B_SZ));
        out[0] = (float)(d_skl - lower);
        g_done = 0u;   // self-restore for next graph replay
    }
}

// ---------------------------------------------------------------------------
extern "C" void kernel_launch(void* const* d_in, const int* in_sizes, int n_in,
                              void* d_out, int out_size)
{
    const float* zl    = (const float*)d_in[0];
    const float* zv    = (const float*)d_in[1];
    const float* fclw  = (const float*)d_in[2];
    const float* fclb  = (const float*)d_in[3];
    const float* fcvw  = (const float*)d_in[4];
    const float* fcvb  = (const float*)d_in[5];
    const float* W1    = (const float*)d_in[6];
    const float* b1    = (const float*)d_in[7];
    const float* W2    = (const float*)d_in[8];
    const float* b2    = (const float*)d_in[9];
    const float* eps1  = (const float*)d_in[10];
    const float* eps2  = (const float*)d_in[11];
    float* out = (float*)d_out;

    k1_fuse<<<B_SZ, 192>>>(zl, zv, fclw, fclb, fcvw, fcvb, eps1, eps2);
    k2_gemm<<<dim3(16, 5, 2), 256>>>(W1, b1);
    k3_pair<<<dim3(16, 16), 256>>>(W2, b2, out);
}

// round 13
// speedup vs baseline: 1.2305x; 1.2305x over previous
#include <cuda_runtime.h>
#include <math.h>

#define B_SZ   1024
#define HID    384
#define MH     300
#define OPAD   320   // padded row stride; cols 300..319 stay zero (zero-init globals)
#define NJT    16

typedef unsigned long long u64;

// Scratch (device globals; allocations forbidden). Zero-initialized at load;
// padding columns are never written, so they remain exactly 0.0f.
__device__ float g_s1[B_SZ * HID];
__device__ float g_s2[B_SZ * HID];
__device__ float g_Axb[B_SZ * OPAD];
__device__ float g_By [B_SZ * OPAD];
__device__ float g_klpart[B_SZ];
__device__ float g_T0[B_SZ];
__device__ float g_rowpart[NJT * B_SZ];   // [jt][i]
__device__ unsigned g_rowdone[16];        // per-row-group arrival counters
__device__ unsigned g_fin;                // finisher counter
__device__ double g_accKL, g_accT0, g_accL;   // distributed accumulators

__device__ __forceinline__ float softplusf(float x) {
    return fmaxf(x, 0.f) + log1pf(expf(-fabsf(x)));
}

// Packed f32x2 ops on u64-resident data
__device__ __forceinline__ u64 f2add_u(u64 a, u64 b) {
    u64 d; asm("add.rn.f32x2 %0, %1, %2;" : "=l"(d) : "l"(a), "l"(b)); return d;
}
__device__ __forceinline__ u64 f2fma_u(u64 a, u64 b, u64 c) {
    u64 d; asm("fma.rn.f32x2 %0, %1, %2, %3;" : "=l"(d) : "l"(a), "l"(b), "l"(c)); return d;
}
__device__ __forceinline__ u64 f2relu_u(u64 a) {
    float lo, hi;
    asm("mov.b64 {%0,%1}, %2;" : "=f"(lo), "=f"(hi) : "l"(a));
    lo = fmaxf(lo, 0.f);
    hi = fmaxf(hi, 0.f);
    u64 d;
    asm("mov.b64 %0, {%1,%2};" : "=l"(d) : "f"(lo), "f"(hi));
    return d;
}
__device__ __forceinline__ float f2hsum(u64 a) {
    float lo, hi;
    asm("mov.b64 {%0,%1}, %2;" : "=f"(lo), "=f"(hi) : "l"(a));
    return lo + hi;
}
__device__ __forceinline__ u64 fpack(float x, float y) {
    u64 d; asm("mov.b64 %0, {%1,%2};" : "=l"(d) : "f"(x), "f"(y)); return d;
}

// ---------------------------------------------------------------------------
// K1: per-batch-row fused  einsum -> (mu,sig) -> sample -> KL partial
// grid 1024, block 192. HBM-bound (176 MB, measured 75% SOL).
// ---------------------------------------------------------------------------
__global__ __launch_bounds__(192) void k1_fuse(
    const float* __restrict__ zl, const float* __restrict__ zv,
    const float* __restrict__ wl_g, const float* __restrict__ bl_g,
    const float* __restrict__ wv_g, const float* __restrict__ bv_g,
    const float* __restrict__ eps1, const float* __restrict__ eps2)
{
    __shared__ float z1s[768], z2s[768];
    __shared__ float wls[20], wvs[36];
    __shared__ float redw[6];
    const int b = blockIdx.x, t = threadIdx.x;
    if (t < 20) wls[t] = wl_g[t];
    if (t >= 32 && t < 68) wvs[t - 32] = wv_g[t - 32];
    __syncthreads();
    const float bl = bl_g[0], bv = bv_g[0];
    {
        const float4* p = (const float4*)(zl + (size_t)b * 20 * 768) + t;
        float4 a = make_float4(bl, bl, bl, bl);
        #pragma unroll
        for (int s = 0; s < 20; ++s) {
            float4 v = p[s * 192];
            float w = wls[s];
            a.x = fmaf(v.x, w, a.x); a.y = fmaf(v.y, w, a.y);
            a.z = fmaf(v.z, w, a.z); a.w = fmaf(v.w, w, a.w);
        }
        ((float4*)z1s)[t] = a;
    }
    {
        const float4* p = (const float4*)(zv + (size_t)b * 36 * 768) + t;
        float4 a = make_float4(bv, bv, bv, bv);
        #pragma unroll
        for (int s = 0; s < 36; ++s) {
            float4 v = p[s * 192];
            float w = wvs[s];
            a.x = fmaf(v.x, w, a.x); a.y = fmaf(v.y, w, a.y);
            a.z = fmaf(v.z, w, a.z); a.w = fmaf(v.w, w, a.w);
        }
        ((float4*)z2s)[t] = a;
    }
    __syncthreads();
    float klacc = 0.f;
    #pragma unroll
    for (int q = 0; q < 2; ++q) {
        int k = t + q * 192;
        float mu1 = z1s[k], mu2 = z2s[k];
        float sg1 = softplusf(z1s[k + HID]) + 1e-7f;
        float sg2 = softplusf(z2s[k + HID]) + 1e-7f;
        float e1 = eps1[b * HID + k], e2 = eps2[b * HID + k];
        float s1v = fmaf(sg1, e1, mu1);
        float s2v = fmaf(sg2, e2, mu2);
        g_s1[b * HID + k] = s1v;
        g_s2[b * HID + k] = s2v;
        float d1 = (s1v - mu2) / sg2;
        float d2 = (s2v - mu1) / sg1;
        klacc += 0.5f * (d1 * d1 + d2 * d2 - e1 * e1 - e2 * e2);
    }
    #pragma unroll
    for (int off = 16; off > 0; off >>= 1)
        klacc += __shfl_xor_sync(0xFFFFFFFFu, klacc, off);
    if ((t & 31) == 0) redw[t >> 5] = klacc;
    __syncthreads();
    if (t == 0)
        g_klpart[b] = redw[0] + redw[1] + redw[2] + redw[3] + redw[4] + redw[5];
}

// ---------------------------------------------------------------------------
// K2: Axb = s1 @ W1x^T + b1 ;  By = s2 @ W1y^T
// grid (16,5,2), block 256. Tile 64x64, u64-packed, 4x4/thread,
// register-prefetch pipeline over 6 k-chunks.
// ---------------------------------------------------------------------------
__global__ __launch_bounds__(256) void k2_gemm(
    const float* __restrict__ W1, const float* __restrict__ b1)
{
    __shared__ u64 As[64][17];
    __shared__ u64 Ws[64][17];

    const int z  = blockIdx.z;
    const int r0 = blockIdx.x * 64;
    const int c0 = blockIdx.y * 64;
    const float* S = z ? g_s2 : g_s1;
    float*       O = z ? g_By : g_Axb;
    const int koff = z ? HID : 0;

    const int t  = threadIdx.x;
    const int tj = t & 15;
    const int ti = t >> 4;

    // prefetch mapping: 512 float4-units per array per chunk; 2/thread each
    const int rP0 = t >> 3,          fP0 = t & 7;
    const int rP1 = (t + 256) >> 3,  fP1 = t & 7;
    const float* srcA0 = &S[(r0 + rP0) * HID + fP0 * 4];
    const float* srcA1 = &S[(r0 + rP1) * HID + fP1 * 4];
    const int  colW0 = c0 + rP0, colW1 = c0 + rP1;
    const bool v0 = colW0 < MH, v1 = colW1 < MH;
    const float* srcW0 = &W1[(v0 ? colW0 : 0) * 768 + koff + fP0 * 4];
    const float* srcW1 = &W1[(v1 ? colW1 : 0) * 768 + koff + fP1 * 4];

    u64 acc[4][4];
    #pragma unroll
    for (int r = 0; r < 4; ++r)
        #pragma unroll
        for (int c = 0; c < 4; ++c) acc[r][c] = 0ull;

    float4 pa0 = *(const float4*)srcA0;
    float4 pa1 = *(const float4*)srcA1;
    float4 pw0 = v0 ? *(const float4*)srcW0 : make_float4(0.f, 0.f, 0.f, 0.f);
    float4 pw1 = v1 ? *(const float4*)srcW1 : make_float4(0.f, 0.f, 0.f, 0.f);

    for (int c = 0; c < 6; ++c) {
        __syncthreads();
        As[rP0][2 * fP0]     = fpack(pa0.x, pa0.y);
        As[rP0][2 * fP0 + 1] = fpack(pa0.z, pa0.w);
        As[rP1][2 * fP1]     = fpack(pa1.x, pa1.y);
        As[rP1][2 * fP1 + 1] = fpack(pa1.z, pa1.w);
        Ws[rP0][2 * fP0]     = fpack(pw0.x, pw0.y);
        Ws[rP0][2 * fP0 + 1] = fpack(pw0.z, pw0.w);
        Ws[rP1][2 * fP1]     = fpack(pw1.x, pw1.y);
        Ws[rP1][2 * fP1 + 1] = fpack(pw1.z, pw1.w);
        __syncthreads();
        if (c < 5) {
            int off = (c + 1) * 32;
            pa0 = *(const float4*)(srcA0 + off);
            pa1 = *(const float4*)(srcA1 + off);
            pw0 = v0 ? *(const float4*)(srcW0 + off) : make_float4(0.f,0.f,0.f,0.f);
            pw1 = v1 ? *(const float4*)(srcW1 + off) : make_float4(0.f,0.f,0.f,0.f);
        }
        #pragma unroll 4
        for (int k2 = 0; k2 < 16; ++k2) {
            u64 a[4], w[4];
            #pragma unroll
            for (int r = 0; r < 4; ++r) a[r] = As[ti + 16 * r][k2];
            #pragma unroll
            for (int cc = 0; cc < 4; ++cc) w[cc] = Ws[tj + 16 * cc][k2];
            #pragma unroll
            for (int r = 0; r < 4; ++r)
                #pragma unroll
                for (int cc = 0; cc < 4; ++cc)
                    acc[r][cc] = f2fma_u(a[r], w[cc], acc[r][cc]);
        }
    }
    #pragma unroll
    for (int r = 0; r < 4; ++r) {
        int row = r0 + ti + 16 * r;
        #pragma unroll
        for (int cc = 0; cc < 4; ++cc) {
            int col = c0 + tj + 16 * cc;
            if (col < MH) {
                float v = f2hsum(acc[r][cc]);
                if (z == 0) v += b1[col];
                O[row * OPAD + col] = v;
            }
        }
    }
}

// ---------------------------------------------------------------------------
// K3: pairwise grid with distributed row-finisher reduction.
// u[i][j] = sum_k relu(Axb[j,k] + By[i,k]) * w2[k]
// grid (16 jt, 16 it), block 256. 64x64 tile, 4x4 pairs/thread, u64-packed,
// register-prefetch pipeline. Diagonal blocks write T0.
// The 16th CTA to finish each row-group reduces that group's 64 rows and
// atomicAdds double partials; the 16th finisher writes out[0].
// ---------------------------------------------------------------------------
__global__ __launch_bounds__(256) void k3_pair(
    const float* __restrict__ W2, const float* __restrict__ b2g,
    float* __restrict__ out)
{
    __shared__ u64 Bys[64][17];
    __shared__ u64 Axs[64][17];
    __shared__ u64 w2s[160];
    __shared__ float rowred[64][17];
    __shared__ int sLast;
    __shared__ double sred[3][2];

    const int jt = blockIdx.x;
    const int it = blockIdx.y;
    const int i0 = it * 64, j0 = jt * 64;
    const int t  = threadIdx.x;
    const int tj = t & 15;
    const int ti = t >> 4;

    if (t < 160) {
        int k = 2 * t;
        float2 w = make_float2(k < MH ? W2[k] : 0.f,
                               k + 1 < MH ? W2[k + 1] : 0.f);
        w2s[t] = *(const u64*)&w;
    }

    const int rA = t >> 3,          fA = t & 7;
    const int rB = (t + 256) >> 3,  fB = t & 7;
    const float* byA = &g_By [(i0 + rA) * OPAD + fA * 4];
    const float* byB = &g_By [(i0 + rB) * OPAD + fB * 4];
    const float* axA = &g_Axb[(j0 + rA) * OPAD + fA * 4];
    const float* axB = &g_Axb[(j0 + rB) * OPAD + fB * 4];

    u64 acc[4][4];
    #pragma unroll
    for (int r = 0; r < 4; ++r)
        #pragma unroll
        for (int c = 0; c < 4; ++c) acc[r][c] = 0ull;

    float4 pb0 = *(const float4*)(byA);
    float4 pb1 = *(const float4*)(byB);
    float4 pa0 = *(const float4*)(axA);
    float4 pa1 = *(const float4*)(axB);

    for (int c = 0; c < 10; ++c) {
        __syncthreads();
        Bys[rA][2 * fA]     = fpack(pb0.x, pb0.y);
        Bys[rA][2 * fA + 1] = fpack(pb0.z, pb0.w);
        Bys[rB][2 * fB]     = fpack(pb1.x, pb1.y);
        Bys[rB][2 * fB + 1] = fpack(pb1.z, pb1.w);
        Axs[rA][2 * fA]     = fpack(pa0.x, pa0.y);
        Axs[rA][2 * fA + 1] = fpack(pa0.z, pa0.w);
        Axs[rB][2 * fB]     = fpack(pa1.x, pa1.y);
        Axs[rB][2 * fB + 1] = fpack(pa1.z, pa1.w);
        __syncthreads();
        if (c < 9) {
            int off = (c + 1) * 32;
            pb0 = *(const float4*)(byA + off);
            pb1 = *(const float4*)(byB + off);
            pa0 = *(const float4*)(axA + off);
            pa1 = *(const float4*)(axB + off);
        }
        #pragma unroll 4
        for (int k2 = 0; k2 < 16; ++k2) {
            u64 wp = w2s[c * 16 + k2];
            u64 a[4], b[4];
            #pragma unroll
            for (int cc = 0; cc < 4; ++cc) a[cc] = Axs[tj + 16 * cc][k2];
            #pragma unroll
            for (int r = 0; r < 4; ++r) b[r] = Bys[ti + 16 * r][k2];
            #pragma unroll
            for (int r = 0; r < 4; ++r)
                #pragma unroll
                for (int cc = 0; cc < 4; ++cc)
                    acc[r][cc] = f2fma_u(f2relu_u(f2add_u(a[cc], b[r])), wp,
                                         acc[r][cc]);
        }
    }

    const float b2v = b2g[0];

    // Diagonal blocks: T0[i] = softplus(u[i][i] + b2)
    if (jt == it && tj == ti) {
        #pragma unroll
        for (int r = 0; r < 4; ++r)
            g_T0[i0 + ti + 16 * r] = softplusf(f2hsum(acc[r][r]) + b2v);
    }

    __syncthreads();
    #pragma unroll
    for (int r = 0; r < 4; ++r) {
        float e = 0.f;
        #pragma unroll
        for (int cc = 0; cc < 4; ++cc)
            e += expf(f2hsum(acc[r][cc]) + b2v);
        rowred[ti + 16 * r][tj] = e;
    }
    __syncthreads();
    if (t < 64) {
        float s = 0.f;
        #pragma unroll
        for (int cc = 0; cc < 16; ++cc) s += rowred[t][cc];
        g_rowpart[jt * B_SZ + i0 + t] = s;
    }

    // ---- row-group finisher: last of the 16 CTAs for row-group `it` ----
    __threadfence();
    __syncthreads();
    if (t == 0) {
        unsigned old = atomicAdd(&g_rowdone[it], 1u);
        sLast = (old == 15u);
    }
    __syncthreads();
    if (!sLast) return;
    __threadfence();   // acquire: all 16 CTAs' rowpart/T0 writes visible

    double kl = 0.0, t0 = 0.0, L = 0.0;
    if (t < 64) {
        int i = i0 + t;
        float rs = 0.f;
        #pragma unroll
        for (int j = 0; j < NJT; ++j)
            rs += g_rowpart[j * B_SZ + i];
        kl = (double)g_klpart[i];
        t0 = (double)g_T0[i];
        // logsumexp_j softplus(u) = log(B + sum_j e^u)
        L  = (double)logf((float)B_SZ + rs);
    }
    if (t < 64) {
        #pragma unroll
        for (int off = 16; off > 0; off >>= 1) {
            kl += __shfl_xor_sync(0xFFFFFFFFu, kl, off);
            t0 += __shfl_xor_sync(0xFFFFFFFFu, t0, off);
            L  += __shfl_xor_sync(0xFFFFFFFFu, L,  off);
        }
        if ((t & 31) == 0) {
            sred[0][t >> 5] = kl; sred[1][t >> 5] = t0; sred[2][t >> 5] = L;
        }
    }
    __syncthreads();
    if (t == 0) {
        atomicAdd(&g_accKL, sred[0][0] + sred[0][1]);
        atomicAdd(&g_accT0, sred[1][0] + sred[1][1]);
        atomicAdd(&g_accL,  sred[2][0] + sred[2][1]);
        __threadfence();
        unsigned old = atomicAdd(&g_fin, 1u);
        if (old == 15u) {
            __threadfence();
            double a = g_accKL, b = g_accT0, c = g_accL;
            double d_skl = a / (double)B_SZ * 0.5;
            double t0m   = b / (double)B_SZ;
            double meanL = c / (double)B_SZ;
            double lower = t0m - (meanL - log((double)B_SZ));
            out[0] = (float)(d_skl - lower);
            // self-restore for next graph replay
            g_accKL = 0.0; g_accT0 = 0.0; g_accL = 0.0;
            g_fin = 0u;
            #pragma unroll
            for (int r = 0; r < 16; ++r) g_rowdone[r] = 0u;
        }
    }
}

// ---------------------------------------------------------------------------
extern "C" void kernel_launch(void* const* d_in, const int* in_sizes, int n_in,
                              void* d_out, int out_size)
{
    const float* zl    = (const float*)d_in[0];
    const float* zv    = (const float*)d_in[1];
    const float* fclw  = (const float*)d_in[2];
    const float* fclb  = (const float*)d_in[3];
    const float* fcvw  = (const float*)d_in[4];
    const float* fcvb  = (const float*)d_in[5];
    const float* W1    = (const float*)d_in[6];
    const float* b1    = (const float*)d_in[7];
    const float* W2    = (const float*)d_in[8];
    const float* b2    = (const float*)d_in[9];
    const float* eps1  = (const float*)d_in[10];
    const float* eps2  = (const float*)d_in[11];
    float* out = (float*)d_out;

    k1_fuse<<<B_SZ, 192>>>(zl, zv, fclw, fclb, fcvw, fcvb, eps1, eps2);
    k2_gemm<<<dim3(16, 5, 2), 256>>>(W1, b1);
    k3_pair<<<dim3(16, 16), 256>>>(W2, b2, out);
}